// round 8
// baseline (speedup 1.0000x reference)
#include <cuda_runtime.h>
#include <cuda_bf16.h>
#include <cstdint>

#define MAXN 100000
#define MAXE 1600000
#define DHID 128
#define SCAN_B 1024
#define MAXBLK 128

// ---------------------------------------------------------------------------
// Scratch (device globals)
// ---------------------------------------------------------------------------
__device__ float g_x1[(size_t)MAXN * DHID];
__device__ float g_x2[(size_t)MAXN * DHID];
__device__ int   g_cnt[MAXN];
__device__ int   g_incl[MAXN];
__device__ int2  g_rc[MAXN];                 // (rowstart, cnt)
__device__ int   g_cursor[MAXN];
__device__ int   g_bsums[MAXBLK];
__device__ int   g_boffs[MAXBLK];
__device__ int2  g_colw[MAXE];               // packed (src, w-bits)
// bf16 weight splits, plain row-major [out 128][k 128]
__device__ unsigned short g_w1hi[16384], g_w1lo[16384];
__device__ unsigned short g_w2hi[16384], g_w2lo[16384];

// ---------------------------------------------------------------------------
__device__ __forceinline__ void mma16816(float* c, const uint32_t* a, const uint32_t* bb) {
    asm volatile(
        "mma.sync.aligned.m16n8k16.row.col.f32.bf16.bf16.f32 "
        "{%0,%1,%2,%3}, {%4,%5,%6,%7}, {%8,%9}, {%0,%1,%2,%3};"
        : "+f"(c[0]), "+f"(c[1]), "+f"(c[2]), "+f"(c[3])
        : "r"(a[0]), "r"(a[1]), "r"(a[2]), "r"(a[3]), "r"(bb[0]), "r"(bb[1]));
}

// ---------------------------------------------------------------------------
// CSR build
// ---------------------------------------------------------------------------
__global__ void count_kernel(const int* __restrict__ dst, int* __restrict__ cnt, int E) {
    int e = blockIdx.x * blockDim.x + threadIdx.x;
    if (e < E) atomicAdd(&cnt[dst[e]], 1);
}

__global__ void __launch_bounds__(SCAN_B)
scan1_kernel(const int* __restrict__ cnt, int* __restrict__ incl,
             int* __restrict__ bsums, int N) {
    __shared__ int s[SCAN_B];
    int tid = threadIdx.x;
    int i = blockIdx.x * SCAN_B + tid;
    int v = (i < N) ? cnt[i] : 0;
    s[tid] = v;
    __syncthreads();
#pragma unroll
    for (int off = 1; off < SCAN_B; off <<= 1) {
        int t = (tid >= off) ? s[tid - off] : 0;
        __syncthreads();
        s[tid] += t;
        __syncthreads();
    }
    if (i < N) incl[i] = s[tid];
    if (tid == SCAN_B - 1) bsums[blockIdx.x] = s[tid];
}

__global__ void __launch_bounds__(MAXBLK)
scan2_kernel(const int* __restrict__ bsums, int* __restrict__ boffs, int nb) {
    __shared__ int s[MAXBLK];
    int tid = threadIdx.x;
    int v = (tid < nb) ? bsums[tid] : 0;
    s[tid] = v;
    __syncthreads();
#pragma unroll
    for (int off = 1; off < MAXBLK; off <<= 1) {
        int t = (tid >= off) ? s[tid - off] : 0;
        __syncthreads();
        s[tid] += t;
        __syncthreads();
    }
    boffs[tid] = s[tid] - v;
}

__global__ void scan3_kernel(const int* __restrict__ incl, const int* __restrict__ cnt,
                             const int* __restrict__ boffs,
                             int2* __restrict__ rc, int* __restrict__ cursor, int N) {
    int i = blockIdx.x * blockDim.x + threadIdx.x;
    if (i < N) {
        int c = cnt[i];
        int rs = incl[i] - c + boffs[i / SCAN_B];
        rc[i] = make_int2(rs, c);
        cursor[i] = rs;
    }
}

__global__ void fill_kernel(const int* __restrict__ src, const int* __restrict__ dst,
                            const float* __restrict__ ew,
                            int* __restrict__ cursor, int2* __restrict__ colw, int E) {
    int e = blockIdx.x * blockDim.x + threadIdx.x;
    if (e < E) {
        int pos = atomicAdd(&cursor[dst[e]], 1);
        colw[pos] = make_int2(src[e], __float_as_int(ew[e]));
    }
}

// ---------------------------------------------------------------------------
// weight split: W -> hi/lo bf16, plain row-major
// ---------------------------------------------------------------------------
__global__ void prep_w_kernel(const float* __restrict__ w1, const float* __restrict__ w2) {
    int idx = blockIdx.x * blockDim.x + threadIdx.x;   // 0 .. 32767
    int which = idx >> 14;
    int e = idx & 16383;
    float v = (which ? w2 : w1)[e];
    __nv_bfloat16 hb = __float2bfloat16(v);
    __nv_bfloat16 lb = __float2bfloat16(v - __bfloat162float(hb));
    if (which) { g_w2hi[e] = __bfloat16_as_ushort(hb); g_w2lo[e] = __bfloat16_as_ushort(lb); }
    else       { g_w1hi[e] = __bfloat16_as_ushort(hb); g_w1lo[e] = __bfloat16_as_ushort(lb); }
}

// ---------------------------------------------------------------------------
// aggregation + combine:  y = (1+eps)*x + mean over in-edges of x[src]*w
// one warp per node; lane owns 4 features (float4 per gather).
// 4 independent edges in flight per iteration (direct loads, no shfl).
// ---------------------------------------------------------------------------
__global__ void __launch_bounds__(256)
agg_kernel(const float* __restrict__ x,
           const int2* __restrict__ rc, const int2* __restrict__ colw,
           const float* __restrict__ eps_ptr, int eps_idx,
           float* __restrict__ y, int N) {
    int t = blockIdx.x * blockDim.x + threadIdx.x;
    int node = t >> 5;
    int lane = t & 31;
    if (node >= N) return;

    int2 rcv = __ldg(&rc[node]);
    int start = rcv.x;
    int c = rcv.y;

    float4 a0 = make_float4(0.f, 0.f, 0.f, 0.f);
    float4 a1 = a0;
    int j = 0;
    for (; j + 3 < c; j += 4) {
        int2 e0 = __ldg(&colw[start + j]);
        int2 e1 = __ldg(&colw[start + j + 1]);
        int2 e2 = __ldg(&colw[start + j + 2]);
        int2 e3 = __ldg(&colw[start + j + 3]);
        float4 v0 = __ldg(reinterpret_cast<const float4*>(x + (size_t)e0.x * DHID) + lane);
        float4 v1 = __ldg(reinterpret_cast<const float4*>(x + (size_t)e1.x * DHID) + lane);
        float4 v2 = __ldg(reinterpret_cast<const float4*>(x + (size_t)e2.x * DHID) + lane);
        float4 v3 = __ldg(reinterpret_cast<const float4*>(x + (size_t)e3.x * DHID) + lane);
        float w0 = __int_as_float(e0.y), w1 = __int_as_float(e1.y);
        float w2 = __int_as_float(e2.y), w3 = __int_as_float(e3.y);
        a0.x += v0.x * w0; a0.y += v0.y * w0; a0.z += v0.z * w0; a0.w += v0.w * w0;
        a1.x += v1.x * w1; a1.y += v1.y * w1; a1.z += v1.z * w1; a1.w += v1.w * w1;
        a0.x += v2.x * w2; a0.y += v2.y * w2; a0.z += v2.z * w2; a0.w += v2.w * w2;
        a1.x += v3.x * w3; a1.y += v3.y * w3; a1.z += v3.z * w3; a1.w += v3.w * w3;
    }
    for (; j < c; j++) {
        int2 e0 = __ldg(&colw[start + j]);
        float w0 = __int_as_float(e0.y);
        float4 v0 = __ldg(reinterpret_cast<const float4*>(x + (size_t)e0.x * DHID) + lane);
        a0.x += v0.x * w0; a0.y += v0.y * w0; a0.z += v0.z * w0; a0.w += v0.w * w0;
    }
    float dinv = (c > 0) ? (1.0f / (float)c) : 0.0f;
    float epsv = 1.0f + eps_ptr[eps_idx];

    float4 xv = __ldg(reinterpret_cast<const float4*>(x + (size_t)node * DHID + lane * 4));
    float4 o;
    o.x = epsv * xv.x + (a0.x + a1.x) * dinv;
    o.y = epsv * xv.y + (a0.y + a1.y) * dinv;
    o.z = epsv * xv.z + (a0.z + a1.z) * dinv;
    o.w = epsv * xv.w + (a0.w + a1.w) * dinv;
    *reinterpret_cast<float4*>(y + (size_t)node * DHID + lane * 4) = o;
}

// ---------------------------------------------------------------------------
// HMMA GEMM:  out = y @ W^T + b  [+relu]
// Block: 256 rows (two 128-row sub-tiles sharing the smem W copy), 256 thr.
// fp32 via split: D = Ahi*Bhi + Ahi*Blo + Alo*Bhi.
// smem: W hi/lo + A hi/lo, each 128 rows x 272B.
// ---------------------------------------------------------------------------
#define PADB 272
#define SM_A_HI 0
#define SM_A_LO 34816
#define SM_B_HI 69632
#define SM_B_LO 104448
#define SM_TOT  139264

__global__ void __launch_bounds__(256)
mm_kernel(const float* __restrict__ y,
          const unsigned short* __restrict__ whi, const unsigned short* __restrict__ wlo,
          const float* __restrict__ b,
          float* __restrict__ out, int n_rows, int do_relu, int zero_row0) {
    extern __shared__ __align__(16) char sm[];
    int tid = threadIdx.x;
    int lane = tid & 31;
    int wid = tid >> 5;

    // copy W hi/lo into padded smem (once per block)
    {
        const uint4* bh = reinterpret_cast<const uint4*>(whi);
        const uint4* bl = reinterpret_cast<const uint4*>(wlo);
#pragma unroll
        for (int i = 0; i < 8; i++) {
            int idx = tid + i * 256;
            int row = idx >> 4;
            int c = idx & 15;
            *reinterpret_cast<uint4*>(sm + SM_B_HI + row * PADB + c * 16) = bh[idx];
            *reinterpret_cast<uint4*>(sm + SM_B_LO + row * PADB + c * 16) = bl[idx];
        }
    }

    int gid = lane >> 2;
    int tig = lane & 3;
    int wr = (wid & 3) * 32;
    int wn = (wid >> 2) * 64;

    const char* pAhi = sm + SM_A_HI + (wr + gid) * PADB + tig * 4;
    const char* pAlo = sm + SM_A_LO + (wr + gid) * PADB + tig * 4;
    const char* pBhi = sm + SM_B_HI + (wn + gid) * PADB + tig * 4;
    const char* pBlo = sm + SM_B_LO + (wn + gid) * PADB + tig * 4;

    for (int sub = 0; sub < 2; sub++) {
        int row0 = blockIdx.x * 256 + sub * 128;
        if (row0 >= n_rows) break;

        // convert A tile: y rows -> hi/lo bf16, padded smem
        {
            int r = tid >> 1;
            int kb = (tid & 1) * 64;
            int grow = row0 + r;
            bool valid = (grow < n_rows);
            const float4* yp = reinterpret_cast<const float4*>(y + (size_t)grow * 128 + kb);
#pragma unroll
            for (int jj = 0; jj < 16; jj++) {
                float4 v = valid ? __ldg(yp + jj) : make_float4(0.f, 0.f, 0.f, 0.f);
                __nv_bfloat16 h0 = __float2bfloat16(v.x), h1 = __float2bfloat16(v.y);
                __nv_bfloat16 h2 = __float2bfloat16(v.z), h3 = __float2bfloat16(v.w);
                __nv_bfloat16 l0 = __float2bfloat16(v.x - __bfloat162float(h0));
                __nv_bfloat16 l1 = __float2bfloat16(v.y - __bfloat162float(h1));
                __nv_bfloat16 l2 = __float2bfloat16(v.z - __bfloat162float(h2));
                __nv_bfloat16 l3 = __float2bfloat16(v.w - __bfloat162float(h3));
                uint2 hp, lp;
                hp.x = ((uint32_t)__bfloat16_as_ushort(h1) << 16) | __bfloat16_as_ushort(h0);
                hp.y = ((uint32_t)__bfloat16_as_ushort(h3) << 16) | __bfloat16_as_ushort(h2);
                lp.x = ((uint32_t)__bfloat16_as_ushort(l1) << 16) | __bfloat16_as_ushort(l0);
                lp.y = ((uint32_t)__bfloat16_as_ushort(l3) << 16) | __bfloat16_as_ushort(l2);
                uint32_t off = (uint32_t)(r * PADB + (kb + jj * 4) * 2);
                *reinterpret_cast<uint2*>(sm + SM_A_HI + off) = hp;
                *reinterpret_cast<uint2*>(sm + SM_A_LO + off) = lp;
            }
        }
        __syncthreads();

        float acc[2][8][4];
#pragma unroll
        for (int mt = 0; mt < 2; mt++)
#pragma unroll
            for (int nt = 0; nt < 8; nt++)
#pragma unroll
                for (int q = 0; q < 4; q++) acc[mt][nt][q] = 0.f;

#pragma unroll
        for (int k = 0; k < 8; k++) {
            int ko = k * 32;
            uint32_t ahi[2][4], alo[2][4];
#pragma unroll
            for (int mt = 0; mt < 2; mt++) {
                int mo = mt * 16 * PADB;
                ahi[mt][0] = *reinterpret_cast<const uint32_t*>(pAhi + mo + ko);
                ahi[mt][1] = *reinterpret_cast<const uint32_t*>(pAhi + mo + 8 * PADB + ko);
                ahi[mt][2] = *reinterpret_cast<const uint32_t*>(pAhi + mo + ko + 16);
                ahi[mt][3] = *reinterpret_cast<const uint32_t*>(pAhi + mo + 8 * PADB + ko + 16);
                alo[mt][0] = *reinterpret_cast<const uint32_t*>(pAlo + mo + ko);
                alo[mt][1] = *reinterpret_cast<const uint32_t*>(pAlo + mo + 8 * PADB + ko);
                alo[mt][2] = *reinterpret_cast<const uint32_t*>(pAlo + mo + ko + 16);
                alo[mt][3] = *reinterpret_cast<const uint32_t*>(pAlo + mo + 8 * PADB + ko + 16);
            }
#pragma unroll
            for (int nt = 0; nt < 8; nt++) {
                int no = nt * 8 * PADB;
                uint32_t bh[2], bl[2];
                bh[0] = *reinterpret_cast<const uint32_t*>(pBhi + no + ko);
                bh[1] = *reinterpret_cast<const uint32_t*>(pBhi + no + ko + 16);
                bl[0] = *reinterpret_cast<const uint32_t*>(pBlo + no + ko);
                bl[1] = *reinterpret_cast<const uint32_t*>(pBlo + no + ko + 16);
#pragma unroll
                for (int mt = 0; mt < 2; mt++) {
                    mma16816(acc[mt][nt], ahi[mt], bh);
                    mma16816(acc[mt][nt], ahi[mt], bl);
                    mma16816(acc[mt][nt], alo[mt], bh);
                }
            }
        }

#pragma unroll
        for (int nt = 0; nt < 8; nt++) {
            int colc = wn + nt * 8 + tig * 2;
            float2 bv = *reinterpret_cast<const float2*>(b + colc);
#pragma unroll
            for (int mt = 0; mt < 2; mt++) {
                int ra = row0 + wr + mt * 16 + gid;
                float2 o0, o1;
                o0.x = acc[mt][nt][0] + bv.x;
                o0.y = acc[mt][nt][1] + bv.y;
                o1.x = acc[mt][nt][2] + bv.x;
                o1.y = acc[mt][nt][3] + bv.y;
                if (do_relu) {
                    o0.x = fmaxf(o0.x, 0.f); o0.y = fmaxf(o0.y, 0.f);
                    o1.x = fmaxf(o1.x, 0.f); o1.y = fmaxf(o1.y, 0.f);
                }
                if (zero_row0 && ra == 0) { o0.x = 0.f; o0.y = 0.f; }
                if (ra < n_rows)
                    *reinterpret_cast<float2*>(out + (size_t)ra * 128 + colc) = o0;
                if (ra + 8 < n_rows)
                    *reinterpret_cast<float2*>(out + (size_t)(ra + 8) * 128 + colc) = o1;
            }
        }
        __syncthreads();   // all warps done with A smem before next sub-tile
    }
}

// ---------------------------------------------------------------------------
extern "C" void kernel_launch(void* const* d_in, const int* in_sizes, int n_in,
                              void* d_out, int out_size) {
    const float* emb    = (const float*)d_in[0];
    const float* w1     = (const float*)d_in[1];
    const float* b1     = (const float*)d_in[2];
    const float* w2     = (const float*)d_in[3];
    const float* b2     = (const float*)d_in[4];
    const float* eps    = (const float*)d_in[5];
    const float* edge_w = (const float*)d_in[6];
    const int*   src    = (const int*)d_in[7];
    const int*   dst    = (const int*)d_in[8];

    int N = in_sizes[0] / DHID;
    int E = in_sizes[6];
    float* out = (float*)d_out;

    float *x1, *x2;
    int *cnt, *incl, *cursor, *bsums, *boffs;
    int2 *rc, *colw;
    unsigned short *w1hi, *w1lo, *w2hi, *w2lo;
    cudaGetSymbolAddress((void**)&x1, g_x1);
    cudaGetSymbolAddress((void**)&x2, g_x2);
    cudaGetSymbolAddress((void**)&cnt, g_cnt);
    cudaGetSymbolAddress((void**)&incl, g_incl);
    cudaGetSymbolAddress((void**)&rc, g_rc);
    cudaGetSymbolAddress((void**)&cursor, g_cursor);
    cudaGetSymbolAddress((void**)&bsums, g_bsums);
    cudaGetSymbolAddress((void**)&boffs, g_boffs);
    cudaGetSymbolAddress((void**)&colw, g_colw);
    cudaGetSymbolAddress((void**)&w1hi, g_w1hi);
    cudaGetSymbolAddress((void**)&w1lo, g_w1lo);
    cudaGetSymbolAddress((void**)&w2hi, g_w2hi);
    cudaGetSymbolAddress((void**)&w2lo, g_w2lo);

    static bool attr_set = false;
    if (!attr_set) {
        cudaFuncSetAttribute(mm_kernel,
                             cudaFuncAttributeMaxDynamicSharedMemorySize, SM_TOT);
        attr_set = true;
    }

    int nb = (N + SCAN_B - 1) / SCAN_B;
    int g_edges = (E + 255) / 256;
    int g_node  = (N + 255) / 256;
    int g_agg   = ((size_t)N * 32 + 255) / 256;
    int g_mm    = (N + 255) / 256;

    // ---- CSR build (memset instead of zero kernel; agg1 is kernel launch #5) ----
    cudaMemsetAsync(cnt, 0, (size_t)N * sizeof(int));
    count_kernel<<<g_edges, 256>>>(dst, cnt, E);
    scan1_kernel<<<nb, SCAN_B>>>(cnt, incl, bsums, N);
    scan2_kernel<<<1, MAXBLK>>>(bsums, boffs, nb);
    scan3_kernel<<<g_node, 256>>>(incl, cnt, boffs, rc, cursor, N);
    fill_kernel<<<g_edges, 256>>>(src, dst, edge_w, cursor, colw, E);

    // ---- layer 1: emb -> x1 (relu) ----
    agg_kernel<<<g_agg, 256>>>(emb, rc, colw, eps, 0, x2, N);
    prep_w_kernel<<<128, 256>>>(w1, w2);
    mm_kernel<<<g_mm, 256, SM_TOT>>>(x2, w1hi, w1lo, b1, x1, N, 1, 0);

    // ---- layer 2: x1 -> x2 (relu) ----
    agg_kernel<<<g_agg, 256>>>(x1, rc, colw, eps, 1, x2, N);
    mm_kernel<<<g_mm, 256, SM_TOT>>>(x2, w2hi, w2lo, b2, x1, N, 1, 0);

    // ---- layer 3: x1 -> out (no relu, row 0 zeroed) ----
    agg_kernel<<<g_agg, 256>>>(x1, rc, colw, eps, 2, x2, N);
    mm_kernel<<<g_mm, 256, SM_TOT>>>(x2, w2hi, w2lo, b2, out, N, 0, 1);
}

// round 9
// speedup vs baseline: 1.1066x; 1.1066x over previous
#include <cuda_runtime.h>
#include <cuda_bf16.h>
#include <cstdint>

#define MAXN 100000
#define MAXE 1600000
#define DHID 128
#define SCAN_B 1024
#define MAXBLK 128

// ---------------------------------------------------------------------------
// Scratch (device globals)
// ---------------------------------------------------------------------------
__device__ float g_x1[(size_t)MAXN * DHID];
__device__ float g_x2[(size_t)MAXN * DHID];
__device__ int   g_cnt[MAXN];
__device__ int   g_incl[MAXN];
__device__ int2  g_rc[MAXN];                 // (rowstart, cnt)
__device__ int   g_cursor[MAXN];
__device__ int   g_bsums[MAXBLK];
__device__ int   g_boffs[MAXBLK];
__device__ int2  g_colw[MAXE];               // packed (src, w-bits)
// bf16 weight splits, plain row-major [out 128][k 128]
__device__ unsigned short g_w1hi[16384], g_w1lo[16384];
__device__ unsigned short g_w2hi[16384], g_w2lo[16384];

// ---------------------------------------------------------------------------
__device__ __forceinline__ void mma16816(float* c, const uint32_t* a, const uint32_t* bb) {
    asm volatile(
        "mma.sync.aligned.m16n8k16.row.col.f32.bf16.bf16.f32 "
        "{%0,%1,%2,%3}, {%4,%5,%6,%7}, {%8,%9}, {%0,%1,%2,%3};"
        : "+f"(c[0]), "+f"(c[1]), "+f"(c[2]), "+f"(c[3])
        : "r"(a[0]), "r"(a[1]), "r"(a[2]), "r"(a[3]), "r"(bb[0]), "r"(bb[1]));
}

// ---------------------------------------------------------------------------
// CSR build
// ---------------------------------------------------------------------------
__global__ void count_kernel(const int* __restrict__ dst, int* __restrict__ cnt, int E) {
    int e = blockIdx.x * blockDim.x + threadIdx.x;
    if (e < E) atomicAdd(&cnt[dst[e]], 1);
}

__global__ void __launch_bounds__(SCAN_B)
scan1_kernel(const int* __restrict__ cnt, int* __restrict__ incl,
             int* __restrict__ bsums, int N) {
    __shared__ int s[SCAN_B];
    int tid = threadIdx.x;
    int i = blockIdx.x * SCAN_B + tid;
    int v = (i < N) ? cnt[i] : 0;
    s[tid] = v;
    __syncthreads();
#pragma unroll
    for (int off = 1; off < SCAN_B; off <<= 1) {
        int t = (tid >= off) ? s[tid - off] : 0;
        __syncthreads();
        s[tid] += t;
        __syncthreads();
    }
    if (i < N) incl[i] = s[tid];
    if (tid == SCAN_B - 1) bsums[blockIdx.x] = s[tid];
}

__global__ void __launch_bounds__(MAXBLK)
scan2_kernel(const int* __restrict__ bsums, int* __restrict__ boffs, int nb) {
    __shared__ int s[MAXBLK];
    int tid = threadIdx.x;
    int v = (tid < nb) ? bsums[tid] : 0;
    s[tid] = v;
    __syncthreads();
#pragma unroll
    for (int off = 1; off < MAXBLK; off <<= 1) {
        int t = (tid >= off) ? s[tid - off] : 0;
        __syncthreads();
        s[tid] += t;
        __syncthreads();
    }
    boffs[tid] = s[tid] - v;
}

__global__ void scan3_kernel(const int* __restrict__ incl, const int* __restrict__ cnt,
                             const int* __restrict__ boffs,
                             int2* __restrict__ rc, int* __restrict__ cursor, int N) {
    int i = blockIdx.x * blockDim.x + threadIdx.x;
    if (i < N) {
        int c = cnt[i];
        int rs = incl[i] - c + boffs[i / SCAN_B];
        rc[i] = make_int2(rs, c);
        cursor[i] = rs;
    }
}

__global__ void fill_kernel(const int* __restrict__ src, const int* __restrict__ dst,
                            const float* __restrict__ ew,
                            int* __restrict__ cursor, int2* __restrict__ colw, int E) {
    int e = blockIdx.x * blockDim.x + threadIdx.x;
    if (e < E) {
        int pos = atomicAdd(&cursor[dst[e]], 1);
        colw[pos] = make_int2(src[e], __float_as_int(ew[e]));
    }
}

// ---------------------------------------------------------------------------
// weight split: W -> hi/lo bf16, plain row-major
// ---------------------------------------------------------------------------
__global__ void prep_w_kernel(const float* __restrict__ w1, const float* __restrict__ w2) {
    int idx = blockIdx.x * blockDim.x + threadIdx.x;   // 0 .. 32767
    int which = idx >> 14;
    int e = idx & 16383;
    float v = (which ? w2 : w1)[e];
    __nv_bfloat16 hb = __float2bfloat16(v);
    __nv_bfloat16 lb = __float2bfloat16(v - __bfloat162float(hb));
    if (which) { g_w2hi[e] = __bfloat16_as_ushort(hb); g_w2lo[e] = __bfloat16_as_ushort(lb); }
    else       { g_w1hi[e] = __bfloat16_as_ushort(hb); g_w1lo[e] = __bfloat16_as_ushort(lb); }
}

// ---------------------------------------------------------------------------
// aggregation + combine:  y = (1+eps)*x + mean over in-edges of x[src]*w
// one warp per node; lane owns 4 features. MLP=2 (empirically optimal:
// deeper batching regressed via cross-CTA L1tex-queue contention, R7/R8).
// ---------------------------------------------------------------------------
__global__ void __launch_bounds__(256)
agg_kernel(const float* __restrict__ x,
           const int2* __restrict__ rc, const int2* __restrict__ colw,
           const float* __restrict__ eps_ptr, int eps_idx,
           float* __restrict__ y, int N) {
    int t = blockIdx.x * blockDim.x + threadIdx.x;
    int node = t >> 5;
    int lane = t & 31;
    if (node >= N) return;

    int2 rcv = __ldg(&rc[node]);
    int start = rcv.x;
    int c = rcv.y;

    float4 a0 = make_float4(0.f, 0.f, 0.f, 0.f);
    float4 a1 = a0;
    int j = 0;
    for (; j + 1 < c; j += 2) {
        int2 e0 = __ldg(&colw[start + j]);
        int2 e1 = __ldg(&colw[start + j + 1]);
        float w0 = __int_as_float(e0.y);
        float w1 = __int_as_float(e1.y);
        float4 v0 = __ldg(reinterpret_cast<const float4*>(x + (size_t)e0.x * DHID) + lane);
        float4 v1 = __ldg(reinterpret_cast<const float4*>(x + (size_t)e1.x * DHID) + lane);
        a0.x += v0.x * w0; a0.y += v0.y * w0; a0.z += v0.z * w0; a0.w += v0.w * w0;
        a1.x += v1.x * w1; a1.y += v1.y * w1; a1.z += v1.z * w1; a1.w += v1.w * w1;
    }
    if (j < c) {
        int2 e0 = __ldg(&colw[start + j]);
        float w0 = __int_as_float(e0.y);
        float4 v0 = __ldg(reinterpret_cast<const float4*>(x + (size_t)e0.x * DHID) + lane);
        a0.x += v0.x * w0; a0.y += v0.y * w0; a0.z += v0.z * w0; a0.w += v0.w * w0;
    }
    float dinv = (c > 0) ? (1.0f / (float)c) : 0.0f;
    float epsv = 1.0f + eps_ptr[eps_idx];

    float4 xv = __ldg(reinterpret_cast<const float4*>(x + (size_t)node * DHID + lane * 4));
    float4 o;
    o.x = epsv * xv.x + (a0.x + a1.x) * dinv;
    o.y = epsv * xv.y + (a0.y + a1.y) * dinv;
    o.z = epsv * xv.z + (a0.z + a1.z) * dinv;
    o.w = epsv * xv.w + (a0.w + a1.w) * dinv;
    *reinterpret_cast<float4*>(y + (size_t)node * DHID + lane * 4) = o;
}

// ---------------------------------------------------------------------------
// HMMA GEMM:  out = y @ W^T + b  [+relu]   (R4-exact: 128 rows/block)
// fp32 via split: D = Ahi*Bhi + Ahi*Blo + Alo*Bhi.
// ---------------------------------------------------------------------------
#define PADB 272
#define SM_A_HI 0
#define SM_A_LO 34816
#define SM_B_HI 69632
#define SM_B_LO 104448
#define SM_TOT  139264

__global__ void __launch_bounds__(256)
mm_kernel(const float* __restrict__ y,
          const unsigned short* __restrict__ whi, const unsigned short* __restrict__ wlo,
          const float* __restrict__ b,
          float* __restrict__ out, int n_rows, int do_relu, int zero_row0) {
    extern __shared__ __align__(16) char sm[];
    int tid = threadIdx.x;
    int lane = tid & 31;
    int wid = tid >> 5;

    {
        const uint4* bh = reinterpret_cast<const uint4*>(whi);
        const uint4* bl = reinterpret_cast<const uint4*>(wlo);
#pragma unroll
        for (int i = 0; i < 8; i++) {
            int idx = tid + i * 256;
            int row = idx >> 4;
            int c = idx & 15;
            *reinterpret_cast<uint4*>(sm + SM_B_HI + row * PADB + c * 16) = bh[idx];
            *reinterpret_cast<uint4*>(sm + SM_B_LO + row * PADB + c * 16) = bl[idx];
        }
    }

    int row0 = blockIdx.x * 128;
    {
        int r = tid >> 1;
        int kb = (tid & 1) * 64;
        int grow = row0 + r;
        bool valid = (grow < n_rows);
        const float4* yp = reinterpret_cast<const float4*>(y + (size_t)grow * 128 + kb);
#pragma unroll
        for (int j = 0; j < 16; j++) {
            float4 v = valid ? __ldg(yp + j) : make_float4(0.f, 0.f, 0.f, 0.f);
            __nv_bfloat16 h0 = __float2bfloat16(v.x), h1 = __float2bfloat16(v.y);
            __nv_bfloat16 h2 = __float2bfloat16(v.z), h3 = __float2bfloat16(v.w);
            __nv_bfloat16 l0 = __float2bfloat16(v.x - __bfloat162float(h0));
            __nv_bfloat16 l1 = __float2bfloat16(v.y - __bfloat162float(h1));
            __nv_bfloat16 l2 = __float2bfloat16(v.z - __bfloat162float(h2));
            __nv_bfloat16 l3 = __float2bfloat16(v.w - __bfloat162float(h3));
            uint2 hp, lp;
            hp.x = ((uint32_t)__bfloat16_as_ushort(h1) << 16) | __bfloat16_as_ushort(h0);
            hp.y = ((uint32_t)__bfloat16_as_ushort(h3) << 16) | __bfloat16_as_ushort(h2);
            lp.x = ((uint32_t)__bfloat16_as_ushort(l1) << 16) | __bfloat16_as_ushort(l0);
            lp.y = ((uint32_t)__bfloat16_as_ushort(l3) << 16) | __bfloat16_as_ushort(l2);
            uint32_t off = (uint32_t)(r * PADB + (kb + j * 4) * 2);
            *reinterpret_cast<uint2*>(sm + SM_A_HI + off) = hp;
            *reinterpret_cast<uint2*>(sm + SM_A_LO + off) = lp;
        }
    }
    __syncthreads();

    int gid = lane >> 2;
    int tig = lane & 3;
    int wr = (wid & 3) * 32;
    int wn = (wid >> 2) * 64;

    const char* pAhi = sm + SM_A_HI + (wr + gid) * PADB + tig * 4;
    const char* pAlo = sm + SM_A_LO + (wr + gid) * PADB + tig * 4;
    const char* pBhi = sm + SM_B_HI + (wn + gid) * PADB + tig * 4;
    const char* pBlo = sm + SM_B_LO + (wn + gid) * PADB + tig * 4;

    float acc[2][8][4];
#pragma unroll
    for (int mt = 0; mt < 2; mt++)
#pragma unroll
        for (int nt = 0; nt < 8; nt++)
#pragma unroll
            for (int q = 0; q < 4; q++) acc[mt][nt][q] = 0.f;

#pragma unroll
    for (int k = 0; k < 8; k++) {
        int ko = k * 32;
        uint32_t ahi[2][4], alo[2][4];
#pragma unroll
        for (int mt = 0; mt < 2; mt++) {
            int mo = mt * 16 * PADB;
            ahi[mt][0] = *reinterpret_cast<const uint32_t*>(pAhi + mo + ko);
            ahi[mt][1] = *reinterpret_cast<const uint32_t*>(pAhi + mo + 8 * PADB + ko);
            ahi[mt][2] = *reinterpret_cast<const uint32_t*>(pAhi + mo + ko + 16);
            ahi[mt][3] = *reinterpret_cast<const uint32_t*>(pAhi + mo + 8 * PADB + ko + 16);
            alo[mt][0] = *reinterpret_cast<const uint32_t*>(pAlo + mo + ko);
            alo[mt][1] = *reinterpret_cast<const uint32_t*>(pAlo + mo + 8 * PADB + ko);
            alo[mt][2] = *reinterpret_cast<const uint32_t*>(pAlo + mo + ko + 16);
            alo[mt][3] = *reinterpret_cast<const uint32_t*>(pAlo + mo + 8 * PADB + ko + 16);
        }
#pragma unroll
        for (int nt = 0; nt < 8; nt++) {
            int no = nt * 8 * PADB;
            uint32_t bh[2], bl[2];
            bh[0] = *reinterpret_cast<const uint32_t*>(pBhi + no + ko);
            bh[1] = *reinterpret_cast<const uint32_t*>(pBhi + no + ko + 16);
            bl[0] = *reinterpret_cast<const uint32_t*>(pBlo + no + ko);
            bl[1] = *reinterpret_cast<const uint32_t*>(pBlo + no + ko + 16);
#pragma unroll
            for (int mt = 0; mt < 2; mt++) {
                mma16816(acc[mt][nt], ahi[mt], bh);
                mma16816(acc[mt][nt], ahi[mt], bl);
                mma16816(acc[mt][nt], alo[mt], bh);
            }
        }
    }

#pragma unroll
    for (int nt = 0; nt < 8; nt++) {
        int colc = wn + nt * 8 + tig * 2;
        float2 bv = *reinterpret_cast<const float2*>(b + colc);
#pragma unroll
        for (int mt = 0; mt < 2; mt++) {
            int ra = row0 + wr + mt * 16 + gid;
            float2 o0, o1;
            o0.x = acc[mt][nt][0] + bv.x;
            o0.y = acc[mt][nt][1] + bv.y;
            o1.x = acc[mt][nt][2] + bv.x;
            o1.y = acc[mt][nt][3] + bv.y;
            if (do_relu) {
                o0.x = fmaxf(o0.x, 0.f); o0.y = fmaxf(o0.y, 0.f);
                o1.x = fmaxf(o1.x, 0.f); o1.y = fmaxf(o1.y, 0.f);
            }
            if (zero_row0 && ra == 0) { o0.x = 0.f; o0.y = 0.f; }
            if (ra < n_rows)
                *reinterpret_cast<float2*>(out + (size_t)ra * 128 + colc) = o0;
            if (ra + 8 < n_rows)
                *reinterpret_cast<float2*>(out + (size_t)(ra + 8) * 128 + colc) = o1;
        }
    }
}

// ---------------------------------------------------------------------------
extern "C" void kernel_launch(void* const* d_in, const int* in_sizes, int n_in,
                              void* d_out, int out_size) {
    const float* emb    = (const float*)d_in[0];
    const float* w1     = (const float*)d_in[1];
    const float* b1     = (const float*)d_in[2];
    const float* w2     = (const float*)d_in[3];
    const float* b2     = (const float*)d_in[4];
    const float* eps    = (const float*)d_in[5];
    const float* edge_w = (const float*)d_in[6];
    const int*   src    = (const int*)d_in[7];
    const int*   dst    = (const int*)d_in[8];

    int N = in_sizes[0] / DHID;
    int E = in_sizes[6];
    float* out = (float*)d_out;

    float *x1, *x2;
    int *cnt, *incl, *cursor, *bsums, *boffs;
    int2 *rc, *colw;
    unsigned short *w1hi, *w1lo, *w2hi, *w2lo;
    cudaGetSymbolAddress((void**)&x1, g_x1);
    cudaGetSymbolAddress((void**)&x2, g_x2);
    cudaGetSymbolAddress((void**)&cnt, g_cnt);
    cudaGetSymbolAddress((void**)&incl, g_incl);
    cudaGetSymbolAddress((void**)&rc, g_rc);
    cudaGetSymbolAddress((void**)&cursor, g_cursor);
    cudaGetSymbolAddress((void**)&bsums, g_bsums);
    cudaGetSymbolAddress((void**)&boffs, g_boffs);
    cudaGetSymbolAddress((void**)&colw, g_colw);
    cudaGetSymbolAddress((void**)&w1hi, g_w1hi);
    cudaGetSymbolAddress((void**)&w1lo, g_w1lo);
    cudaGetSymbolAddress((void**)&w2hi, g_w2hi);
    cudaGetSymbolAddress((void**)&w2lo, g_w2lo);

    static bool attr_set = false;
    if (!attr_set) {
        cudaFuncSetAttribute(mm_kernel,
                             cudaFuncAttributeMaxDynamicSharedMemorySize, SM_TOT);
        attr_set = true;
    }

    int nb = (N + SCAN_B - 1) / SCAN_B;
    int g_edges = (E + 255) / 256;
    int g_node  = (N + 255) / 256;
    int g_agg   = ((size_t)N * 32 + 255) / 256;
    int g_mm    = (N + 127) / 128;

    // ---- CSR build + weight prep ----
    cudaMemsetAsync(cnt, 0, (size_t)N * sizeof(int));
    count_kernel<<<g_edges, 256>>>(dst, cnt, E);
    prep_w_kernel<<<128, 256>>>(w1, w2);
    scan1_kernel<<<nb, SCAN_B>>>(cnt, incl, bsums, N);
    scan2_kernel<<<1, MAXBLK>>>(bsums, boffs, nb);
    scan3_kernel<<<g_node, 256>>>(incl, cnt, boffs, rc, cursor, N);
    fill_kernel<<<g_edges, 256>>>(src, dst, edge_w, cursor, colw, E);

    // ---- layer 1: emb -> x1 (relu) ----
    agg_kernel<<<g_agg, 256>>>(emb, rc, colw, eps, 0, x2, N);
    mm_kernel<<<g_mm, 256, SM_TOT>>>(x2, w1hi, w1lo, b1, x1, N, 1, 0);

    // ---- layer 2: x1 -> x2 (relu) ----
    agg_kernel<<<g_agg, 256>>>(x1, rc, colw, eps, 1, x2, N);
    mm_kernel<<<g_mm, 256, SM_TOT>>>(x2, w2hi, w2lo, b2, x1, N, 1, 0);

    // ---- layer 3: x1 -> out (no relu, row 0 zeroed) ----
    agg_kernel<<<g_agg, 256>>>(x1, rc, colw, eps, 2, x2, N);
    mm_kernel<<<g_mm, 256, SM_TOT>>>(x2, w2hi, w2lo, b2, out, N, 0, 1);
}